// round 1
// baseline (speedup 1.0000x reference)
#include <cuda_runtime.h>

// MXFP4 (E2M1) block fake-quant embedding gather.
// d_in[0]: int32 indices, (4,4096) flattened -> 16384 tokens
// d_in[1]: float32 embedding table, (50257, 1024)
// d_out  : float32 (16384, 1024)
//
// Per 32-feature block: scale = max|x|/6 (1 if max==0), round |x/scale| to the
// nearest E2M1 grid point {0,0.5,1,1.5,2,3,4,6} (ties toward the lower point,
// matching searchsorted side='left'), rescale, keep sign.

__device__ __forceinline__ float fp4_round(float x, float scale) {
    float s = x / scale;           // IEEE division, matches reference x/scale
    float a = fabsf(s);
    // strict '>' on the midpoints == searchsorted(bounds, a, side='left')
    float g;
    if (a > 1.75f) {
        g = (a > 3.5f) ? ((a > 5.0f) ? 6.0f : 4.0f)
                       : ((a > 2.5f) ? 3.0f : 2.0f);
    } else {
        g = (a > 0.75f) ? ((a > 1.25f) ? 1.5f : 1.0f)
                        : ((a > 0.25f) ? 0.5f : 0.0f);
    }
    return copysignf(g * scale, s);
}

__global__ void mxfp4_embed_kernel(const int* __restrict__ idx,
                                   const float* __restrict__ emb,
                                   float* __restrict__ out,
                                   int F_div4) {
    const int token = blockIdx.x;
    const int row = idx[token];                 // broadcast load
    const int t = threadIdx.x;                  // 0..F/4-1

    const float4* src = reinterpret_cast<const float4*>(emb) +
                        (size_t)row * F_div4;
    float4* dst = reinterpret_cast<float4*>(out) + (size_t)token * F_div4;

    float4 v = src[t];

    // local max |.| over this thread's 4 values
    float m = fmaxf(fmaxf(fabsf(v.x), fabsf(v.y)),
                    fmaxf(fabsf(v.z), fabsf(v.w)));
    // reduce over the 8-lane group covering one 32-element block
    #pragma unroll
    for (int o = 4; o > 0; o >>= 1)
        m = fmaxf(m, __shfl_xor_sync(0xFFFFFFFFu, m, o, 8));

    const float scale = (m == 0.0f) ? 1.0f : (m / 6.0f);

    float4 r;
    r.x = fp4_round(v.x, scale);
    r.y = fp4_round(v.y, scale);
    r.z = fp4_round(v.z, scale);
    r.w = fp4_round(v.w, scale);

    dst[t] = r;
}

extern "C" void kernel_launch(void* const* d_in, const int* in_sizes, int n_in,
                              void* d_out, int out_size) {
    const int*   idx = (const int*)d_in[0];
    const float* emb = (const float*)d_in[1];
    float*       out = (float*)d_out;

    const int tokens = in_sizes[0];          // 16384
    const int F      = out_size / tokens;    // 1024
    const int F4     = F / 4;                // 256 threads per CTA

    mxfp4_embed_kernel<<<tokens, F4>>>(idx, emb, out, F4);
}

// round 2
// speedup vs baseline: 1.3692x; 1.3692x over previous
#include <cuda_runtime.h>

// MXFP4 (E2M1) block fake-quant embedding gather — R2: 4 tokens/CTA, MLP=4.
// d_in[0]: int32 indices, 16384 tokens
// d_in[1]: float32 embedding table, (50257, 1024)
// d_out  : float32 (16384, 1024)

#define F        1024
#define TOK_CTA  4

__device__ __forceinline__ float fp4_round(float x, float scale) {
    float s = x / scale;           // IEEE division, matches reference x/scale
    float a = fabsf(s);
    // strict '>' on midpoints == searchsorted(bounds, |s|, side='left')
    float g;
    if (a > 1.75f) {
        g = (a > 3.5f) ? ((a > 5.0f) ? 6.0f : 4.0f)
                       : ((a > 2.5f) ? 3.0f : 2.0f);
    } else {
        g = (a > 0.75f) ? ((a > 1.25f) ? 1.5f : 1.0f)
                        : ((a > 0.25f) ? 0.5f : 0.0f);
    }
    return copysignf(g * scale, s);
}

__global__ void __launch_bounds__(256)
mxfp4_embed_kernel(const int* __restrict__ idx,
                   const float* __restrict__ emb,
                   float* __restrict__ out) {
    const int t = threadIdx.x;                      // 0..255, one float4 per row
    const int base = blockIdx.x * TOK_CTA;

    // Front-batch the index loads (uniform across CTA -> L1 broadcast)
    int rows[TOK_CTA];
    #pragma unroll
    for (int j = 0; j < TOK_CTA; j++)
        rows[j] = __ldg(&idx[base + j]);

    // Front-batch 4 independent row loads -> MLP=4
    float4 v[TOK_CTA];
    #pragma unroll
    for (int j = 0; j < TOK_CTA; j++)
        v[j] = reinterpret_cast<const float4*>(emb)[(size_t)rows[j] * (F / 4) + t];

    float4* dst = reinterpret_cast<float4*>(out) + (size_t)base * (F / 4) + t;

    #pragma unroll
    for (int j = 0; j < TOK_CTA; j++) {
        // max |.| over this thread's 4 values
        float m = fmaxf(fmaxf(fabsf(v[j].x), fabsf(v[j].y)),
                        fmaxf(fabsf(v[j].z), fabsf(v[j].w)));
        // reduce over the 8-lane group covering one 32-element block
        #pragma unroll
        for (int o = 4; o > 0; o >>= 1)
            m = fmaxf(m, __shfl_xor_sync(0xFFFFFFFFu, m, o, 8));

        const float scale = (m == 0.0f) ? 1.0f : (m / 6.0f);

        float4 r;
        r.x = fp4_round(v[j].x, scale);
        r.y = fp4_round(v[j].y, scale);
        r.z = fp4_round(v[j].z, scale);
        r.w = fp4_round(v[j].w, scale);

        dst[(size_t)j * (F / 4)] = r;
    }
}

extern "C" void kernel_launch(void* const* d_in, const int* in_sizes, int n_in,
                              void* d_out, int out_size) {
    const int*   idx = (const int*)d_in[0];
    const float* emb = (const float*)d_in[1];
    float*       out = (float*)d_out;

    const int tokens = in_sizes[0];              // 16384
    mxfp4_embed_kernel<<<tokens / TOK_CTA, 256>>>(idx, emb, out);
}